// round 12
// baseline (speedup 1.0000x reference)
#include <cuda_runtime.h>
#include <math.h>

#define GXN 128
#define GYN 128
#define NA 9
#define NCELLS (32 * 128 * 128)            // 524288
#define TPB 128
#define NWARPS (TPB / 32)                  // 4
#define WT_CELLS 32                        // cells per warp-tile
#define NWTILES (NCELLS / WT_CELLS)        // 16384
#define OUT_FLOATS (WT_CELLS * 45)         // 1440
#define TGT_FLOATS (WT_CELLS * 18)         // 576
#define BUF_FLOATS (OUT_FLOATS + TGT_FLOATS) // 2016
#define OUT_BYTES (OUT_FLOATS * 4)         // 5760
#define TGT_BYTES (TGT_FLOATS * 4)         // 2304
#define BUF_BYTES (BUF_FLOATS * 4)         // 8064
#define NBUF 3
#define GRID 296                           // 2 CTAs/SM * 148 SMs
#define NSTREAMS (GRID * NWARPS)           // 1184 warp-streams

__device__ double g_acc[5];
__device__ unsigned int g_count = 0;

__device__ __forceinline__ unsigned smem_u32(const void* p) {
    return (unsigned)__cvta_generic_to_shared(p);
}
__device__ __forceinline__ void mbar_init(unsigned mbar, unsigned count) {
    asm volatile("mbarrier.init.shared.b64 [%0], %1;" :: "r"(mbar), "r"(count) : "memory");
}
__device__ __forceinline__ void mbar_expect_tx(unsigned mbar, unsigned bytes) {
    asm volatile("mbarrier.arrive.expect_tx.shared.b64 _, [%0], %1;"
                 :: "r"(mbar), "r"(bytes) : "memory");
}
__device__ __forceinline__ void bulk_copy(unsigned dst_smem, const void* gsrc,
                                          unsigned bytes, unsigned mbar) {
    asm volatile(
        "cp.async.bulk.shared::cta.global.mbarrier::complete_tx::bytes [%0], [%1], %2, [%3];"
        :: "r"(dst_smem), "l"(gsrc), "r"(bytes), "r"(mbar) : "memory");
}
__device__ __forceinline__ void mbar_wait(unsigned mbar, unsigned phase) {
    unsigned done;
    asm volatile(
        "{\n\t.reg .pred p;\n\t"
        "mbarrier.try_wait.parity.acquire.cta.shared::cta.b64 p, [%1], %2;\n\t"
        "selp.b32 %0, 1, 0, p;\n\t}"
        : "=r"(done) : "r"(mbar), "r"(phase) : "memory");
    if (!done) {
        asm volatile(
            "{\n\t.reg .pred P1;\n\t"
            "WAIT_LOOP_%=:\n\t"
            "mbarrier.try_wait.parity.acquire.cta.shared::cta.b64 P1, [%0], %1, 0x989680;\n\t"
            "@P1 bra.uni WAIT_DONE_%=;\n\t"
            "bra.uni WAIT_LOOP_%=;\n\t"
            "WAIT_DONE_%=:\n\t}"
            :: "r"(mbar), "r"(phase) : "memory");
    }
}

// Issue both bulk copies for one warp-tile into one ring slot (elected lane).
__device__ __forceinline__ void issue_wtile(const float* __restrict__ out,
                                            const float* __restrict__ target,
                                            int wtile, unsigned dst, unsigned mbar)
{
    mbar_expect_tx(mbar, BUF_BYTES);
    bulk_copy(dst, out + (size_t)wtile * OUT_FLOATS, OUT_BYTES, mbar);
    bulk_copy(dst + OUT_BYTES, target + (size_t)wtile * TGT_FLOATS, TGT_BYTES, mbar);
}

__global__ __launch_bounds__(TPB) void loss_kernel(
    const float* __restrict__ out,
    const float* __restrict__ target,
    float* __restrict__ o)
{
    extern __shared__ float s_buf[];   // NWARPS * NBUF * 2016 floats = 96768 B
    // warp w, slot b at s_buf + (w*NBUF + b)*BUF_FLOATS
    // per slot: [0:1440) out cells, [1440:2016) target cells

    __shared__ float s_cellp[NWARPS][WT_CELLS][8];   // 4096 B
    __shared__ float s_red[NWARPS][5];
    __shared__ int s_islast;
    __shared__ __align__(8) unsigned long long s_mbar[NWARPS][NBUF];

    const int tid = threadIdx.x;
    const int warp = tid >> 5;
    const int lane = tid & 31;
    const unsigned FULL = 0xFFFFFFFFu;

    // This warp's stream of warp-tiles: gw, gw+NSTREAMS, gw+2*NSTREAMS, ...
    const int gw = blockIdx.x * NWARPS + warp;
    const int nt = (gw < NWTILES % NSTREAMS) ? (NWTILES / NSTREAMS + 1)
                                             : (NWTILES / NSTREAMS);

    if (tid < NWARPS * NBUF)
        mbar_init(smem_u32(&s_mbar[tid / NBUF][tid % NBUF]), 1);
    __syncthreads();

    // ---- Prologue: this warp's elected lane fills its own ring ----
    if (lane == 0) {
        #pragma unroll
        for (int b = 0; b < NBUF; b++) {
            if (b < nt)
                issue_wtile(out, target, gw + b * NSTREAMS,
                            smem_u32(s_buf + (warp * NBUF + b) * BUF_FLOATS),
                            smem_u32(&s_mbar[warp][b]));
        }
    }
    __syncwarp();

    float acc_allloss = 0.0f;
    float acc_jbb = 0.0f;
    float acc_huhuh = 0.0f;
    float acc_zsd = 0.0f;
    float acc_npos = 0.0f;

    const float FOUR_OVER_PI2 = 4.0f / (3.14159265358979323846f * 3.14159265358979323846f);

    for (int i = 0; i < nt; i++) {
        const int wtile = gw + i * NSTREAMS;
        const int b = i % NBUF;
        const unsigned phase = (unsigned)(i / NBUF) & 1u;
        float* bb = s_buf + (warp * NBUF + b) * BUF_FLOATS;
        const float* stg = bb + OUT_FLOATS + lane * 18;

        mbar_wait(smem_u32(&s_mbar[warp][b]), phase);

        const int cellc = wtile * WT_CELLS + lane;
        const float st5 = stg[5];
        const bool pos = st5 > 0.8f;
        const unsigned m = __ballot_sync(FULL, pos);
        const int nP = __popc(m);

        if (pos) {
            const int off = __popc(m & ((1u << lane) - 1u));
            const int gy = cellc & 127;
            const int gx = (cellc >> 7) & 127;

            const float st0 = stg[0];
            const float st1 = stg[1];
            const float st2 = stg[2];
            const float st3 = stg[3];

            const float ax1 = st0 - st2 * 0.5f;
            const float ax2 = st0 + st2 * 0.5f;
            const float ay1 = st1 - st3 * 0.5f;
            const float ay2 = st1 + st3 * 0.5f;
            const float atana = atanf(__fdividef(ax2 - ax1, ay2 - ay1));
            const float zx = (float)gx * (1.0f / GXN) + 1.0f / (2.0f * GXN);
            const float zy = (float)gy * (1.0f / GYN) + 1.0f / (2.0f * GYN);

            float* p = s_cellp[warp][off];
            p[0] = ax1; p[1] = ax2; p[2] = ay1; p[3] = ay2;
            p[4] = atana; p[5] = zx; p[6] = zy;
            p[7] = __int_as_float(lane * 45);
            acc_npos += 1.0f;
        } else {
            const float* s = bb + lane * 45;
            #pragma unroll
            for (int a = 0; a < NA; a++) {
                const float obj = s[a * 5 + 4];
                acc_zsd += obj * obj;
            }
        }
        __syncwarp();

        // ---- Heavy sweep: nP*9 work items across this warp-tile's 32 cells ----
        const int items = nP * NA;
        for (int bo = 0; bo < items; bo += 32) {
            const int ii = bo + lane;
            if (ii < items) {
                const int r = ii / 9;
                const int a = ii - r * 9;
                const float* p = s_cellp[warp][r];
                const float ax1 = p[0], ax2 = p[1], ay1 = p[2], ay2 = p[3];
                const float atana = p[4], zx = p[5], zy = p[6];
                const int coff = __float_as_int(p[7]);

                const float* s = bb + coff + a * 5;
                const float o0 = s[0];
                const float o1 = s[1];
                const float o2 = s[2];
                const float o3 = s[3];
                const float obj = s[4];

                const float area_a = (ax2 - ax1) * (ay2 - ay1);
                const float acx = (ax1 + ax2) * 0.5f;
                const float acy = (ay1 + ay2) * 0.5f;

                const float bcx = o0 - 0.5f + zx;
                const float bcy = o1 - 0.5f + zy;
                const float bw  = o2 - 0.5f + (1.0f / GXN);
                const float bh  = o3 - 0.5f + (1.0f / GYN);
                const float bx1 = bcx - bw * 0.5f;
                const float bx2 = bcx + bw * 0.5f;
                const float by1 = bcy - bh * 0.5f;
                const float by2 = bcy + bh * 0.5f;

                const float iw = fminf(ax2, bx2) - fmaxf(ax1, bx1);
                const float ih = fminf(ay2, by2) - fmaxf(ay1, by1);
                const float cross = (iw > 0.0f && ih > 0.0f) ? iw * ih : 0.0f;
                const float area_b = (bx2 - bx1) * (by2 - by1);
                const float uni = area_a + area_b - cross;
                const float iou = __fdividef(cross, uni + 1e-6f);

                const float dx = bcx - acx;
                const float dy = bcy - acy;
                const float d2 = dx * dx + dy * dy;

                const float cw = fmaxf(ax2, bx2) - fminf(ax1, bx1);
                const float ch = fmaxf(ay2, by2) - fminf(ay1, by1);
                const float c2 = cw * cw + ch * ch;

                const float diou = iou - __fdividef(d2, c2);

                const float da = atana - atanf(__fdividef(bx2 - bx1, by2 - by1));
                const float v = FOUR_OVER_PI2 * da * da;
                const float alpha = __fdividef(v, 1.0f - iou + v);
                const float los = 1.0f - (diou - alpha * v);

                const float om = 1.0f - obj;
                acc_allloss += los + om;
                acc_jbb += iou;
                acc_huhuh += om;
                acc_zsd += om * om;
            }
        }
        __syncwarp();   // all lanes done with this buffer

        // ---- Warp-private refill: no cross-warp dependency ----
        if (lane == 0 && i + NBUF < nt) {
            issue_wtile(out, target, gw + (i + NBUF) * NSTREAMS,
                        smem_u32(bb), smem_u32(&s_mbar[warp][b]));
        }
    }

    // ---- Block reduction (once per block) ----
    float vals[5];
    vals[0] = acc_allloss;
    vals[1] = acc_jbb;
    vals[2] = acc_huhuh;
    vals[3] = acc_zsd;
    vals[4] = acc_npos;

    #pragma unroll
    for (int kk = 0; kk < 5; kk++) {
        float v = vals[kk];
        v += __shfl_xor_sync(FULL, v, 16);
        v += __shfl_xor_sync(FULL, v, 8);
        v += __shfl_xor_sync(FULL, v, 4);
        v += __shfl_xor_sync(FULL, v, 2);
        v += __shfl_xor_sync(FULL, v, 1);
        vals[kk] = v;
    }
    if (lane == 0) {
        #pragma unroll
        for (int kk = 0; kk < 5; kk++) s_red[warp][kk] = vals[kk];
    }
    __syncthreads();

    if (warp == 0 && lane < 5) {
        float v = 0.0f;
        #pragma unroll
        for (int w = 0; w < NWARPS; w++) v += s_red[w][lane];
        atomicAdd(&g_acc[lane], (double)v);
    }
    __syncthreads();

    // ---- Last block finalizes and resets for next graph replay ----
    if (tid == 0) {
        __threadfence();
        const unsigned done = atomicAdd(&g_count, 1u);
        s_islast = (done == (unsigned)(gridDim.x - 1)) ? 1 : 0;
    }
    __syncthreads();

    if (s_islast && tid == 0) {
        const double a0 = atomicAdd(&g_acc[0], 0.0);
        const double a1 = atomicAdd(&g_acc[1], 0.0);
        const double a2 = atomicAdd(&g_acc[2], 0.0);
        const double a3 = atomicAdd(&g_acc[3], 0.0);
        const double npos = atomicAdd(&g_acc[4], 0.0);

        const double jsq = npos * (double)NA;
        const double qit = ((double)NCELLS - npos) * (double)NA;
        o[0] = (float)(a0 / jsq + a3 / (jsq + qit));
        o[1] = (float)(a1 / jsq);
        o[2] = (float)(a2 / jsq);

        g_acc[0] = 0.0; g_acc[1] = 0.0; g_acc[2] = 0.0;
        g_acc[3] = 0.0; g_acc[4] = 0.0;
        __threadfence();
        g_count = 0u;
    }
}

extern "C" void kernel_launch(void* const* d_in, const int* in_sizes, int n_in,
                              void* d_out, int out_size) {
    const float* out_t = (const float*)d_in[0];
    const float* target = (const float*)d_in[1];
    float* o = (float*)d_out;

    const int smem_bytes = NWARPS * NBUF * BUF_FLOATS * (int)sizeof(float); // 96768
    static int configured = 0;
    if (!configured) {
        cudaFuncSetAttribute(loss_kernel,
                             cudaFuncAttributeMaxDynamicSharedMemorySize,
                             smem_bytes);
        configured = 1;
    }
    loss_kernel<<<GRID, TPB, smem_bytes>>>(out_t, target, o);
}

// round 13
// speedup vs baseline: 1.2279x; 1.2279x over previous
#include <cuda_runtime.h>
#include <math.h>

#define GXN 128
#define GYN 128
#define NA 9
#define NCELLS (32 * 128 * 128)            // 524288
#define TPB 256
#define NWARPS (TPB / 32)                  // 8
#define TILE_CELLS 128
#define NTILES (NCELLS / TILE_CELLS)       // 4096
#define CPW (TILE_CELLS / NWARPS)          // 16 cells per warp
#define OUT_FLOATS (TILE_CELLS * 45)       // 5760
#define TGT_FLOATS (TILE_CELLS * 18)       // 2304
#define BUF_FLOATS (OUT_FLOATS + TGT_FLOATS) // 8064
#define OUT_BYTES (OUT_FLOATS * 4)         // 23040
#define TGT_BYTES (TGT_FLOATS * 4)         // 9216
#define BUF_BYTES (BUF_FLOATS * 4)         // 32256
#define NBUF 3
#define GRID 296                           // 2 CTAs/SM * 148 SMs

__device__ double g_acc[5];
__device__ unsigned int g_count = 0;

__device__ __forceinline__ unsigned smem_u32(const void* p) {
    return (unsigned)__cvta_generic_to_shared(p);
}
__device__ __forceinline__ void mbar_init(unsigned mbar, unsigned count) {
    asm volatile("mbarrier.init.shared.b64 [%0], %1;" :: "r"(mbar), "r"(count) : "memory");
}
__device__ __forceinline__ void mbar_expect_tx(unsigned mbar, unsigned bytes) {
    asm volatile("mbarrier.arrive.expect_tx.shared.b64 _, [%0], %1;"
                 :: "r"(mbar), "r"(bytes) : "memory");
}
__device__ __forceinline__ void bulk_copy(unsigned dst_smem, const void* gsrc,
                                          unsigned bytes, unsigned mbar) {
    asm volatile(
        "cp.async.bulk.shared::cta.global.mbarrier::complete_tx::bytes [%0], [%1], %2, [%3];"
        :: "r"(dst_smem), "l"(gsrc), "r"(bytes), "r"(mbar) : "memory");
}
__device__ __forceinline__ void mbar_wait(unsigned mbar, unsigned phase) {
    unsigned done;
    asm volatile(
        "{\n\t.reg .pred p;\n\t"
        "mbarrier.try_wait.parity.acquire.cta.shared::cta.b64 p, [%1], %2;\n\t"
        "selp.b32 %0, 1, 0, p;\n\t}"
        : "=r"(done) : "r"(mbar), "r"(phase) : "memory");
    if (!done) {
        asm volatile(
            "{\n\t.reg .pred P1;\n\t"
            "WAIT_LOOP_%=:\n\t"
            "mbarrier.try_wait.parity.acquire.cta.shared::cta.b64 P1, [%0], %1, 0x989680;\n\t"
            "@P1 bra.uni WAIT_DONE_%=;\n\t"
            "bra.uni WAIT_LOOP_%=;\n\t"
            "WAIT_DONE_%=:\n\t}"
            :: "r"(mbar), "r"(phase) : "memory");
    }
}

__device__ __forceinline__ void issue_tile(const float* __restrict__ out,
                                           const float* __restrict__ target,
                                           int tile, unsigned dst, unsigned mbar)
{
    mbar_expect_tx(mbar, BUF_BYTES);
    bulk_copy(dst, out + (size_t)tile * OUT_FLOATS, OUT_BYTES, mbar);
    bulk_copy(dst + OUT_BYTES, target + (size_t)tile * TGT_FLOATS, TGT_BYTES, mbar);
}

__global__ __launch_bounds__(TPB) void loss_kernel(
    const float* __restrict__ out,
    const float* __restrict__ target,
    float* __restrict__ o)
{
    extern __shared__ float s_buf[];   // NBUF * 8064 floats = 96768 B
    // per slot: [0:5760) out tile, [5760:8064) target tile

    __shared__ float s_cellp[NWARPS][CPW][8];   // 4096 B
    __shared__ float s_red[NWARPS][5];
    __shared__ int s_islast;
    __shared__ __align__(8) unsigned long long s_mbar[NBUF];

    const int tid = threadIdx.x;
    const int warp = tid >> 5;
    const int lane = tid & 31;
    const unsigned FULL = 0xFFFFFFFFu;

    const unsigned mbar_base = smem_u32(&s_mbar[0]);
    const unsigned buf_base = smem_u32(s_buf);

    const int bid = blockIdx.x;
    const int nt = (bid < NTILES % GRID) ? (NTILES / GRID + 1) : (NTILES / GRID);

    if (tid < NBUF) mbar_init(mbar_base + tid * 8, 1);
    __syncthreads();

    if (tid == 0) {
        #pragma unroll
        for (int b = 0; b < NBUF; b++) {
            if (b < nt)
                issue_tile(out, target, bid + b * GRID,
                           buf_base + b * BUF_BYTES, mbar_base + b * 8);
        }
    }

    float acc_allloss = 0.0f;
    float acc_jbb = 0.0f;
    float acc_huhuh = 0.0f;
    float acc_zsd = 0.0f;
    float acc_npos = 0.0f;

    const float FOUR_OVER_PI2 = 4.0f / (3.14159265358979323846f * 3.14159265358979323846f);

    int b = 0;                 // ring slot
    unsigned phase = 0;        // parity of current slot's cycle
    for (int i = 0; i < nt; i++) {
        const int tile = bid + i * GRID;
        float* bb = s_buf + b * BUF_FLOATS;
        float* wbuf = bb + warp * (CPW * 45);

        mbar_wait(mbar_base + b * 8, phase);

        // 16 cells per warp: lanes 0..15 own one cell each (providers);
        // negative path uses 2 lanes per cell (anchors split 5/4).
        const int c = lane & 15;
        const int half = lane >> 4;
        const int cellc = tile * TILE_CELLS + warp * CPW + c;
        const float* stg = bb + OUT_FLOATS + (warp * CPW + c) * 18;

        const float st5 = stg[5];
        const bool owner = lane < CPW;
        const bool pos_c = st5 > 0.8f;
        const unsigned m = __ballot_sync(FULL, owner && pos_c) & 0xFFFFu;
        const int nP = __popc(m);

        if (owner && pos_c) {
            const int off = __popc(m & ((1u << lane) - 1u));
            const int gy = cellc & 127;
            const int gx = (cellc >> 7) & 127;

            const float st0 = stg[0];
            const float st1 = stg[1];
            const float st2 = stg[2];
            const float st3 = stg[3];

            const float ax1 = st0 - st2 * 0.5f;
            const float ax2 = st0 + st2 * 0.5f;
            const float ay1 = st1 - st3 * 0.5f;
            const float ay2 = st1 + st3 * 0.5f;
            const float atana = atanf(__fdividef(ax2 - ax1, ay2 - ay1));
            const float zx = (float)gx * (1.0f / GXN) + 1.0f / (2.0f * GXN);
            const float zy = (float)gy * (1.0f / GYN) + 1.0f / (2.0f * GYN);

            float* p = s_cellp[warp][off];
            p[0] = ax1; p[1] = ax2; p[2] = ay1; p[3] = ay2;
            p[4] = atana; p[5] = zx; p[6] = zy;
            p[7] = __int_as_float(c * 45);
            acc_npos += 1.0f;
        }
        if (!pos_c) {
            // negative path: 2 lanes per cell, anchors 0..4 / 5..8
            const float* s = wbuf + c * 45 + (half ? 25 : 0);
            #pragma unroll
            for (int j = 0; j < 5; j++) {
                if (j < 4 || !half) {
                    const float obj = s[j * 5 + 4];
                    acc_zsd += obj * obj;
                }
            }
        }
        __syncwarp();

        // ---- Heavy sweep: nP*9 work items (nP<=16 -> usually 1 pass) ----
        const int items = nP * NA;
        for (int bo = 0; bo < items; bo += 32) {
            const int ii = bo + lane;
            if (ii < items) {
                const int r = ii / 9;
                const int a = ii - r * 9;
                const float* p = s_cellp[warp][r];
                const float ax1 = p[0], ax2 = p[1], ay1 = p[2], ay2 = p[3];
                const float atana = p[4], zx = p[5], zy = p[6];
                const int coff = __float_as_int(p[7]);

                const float* s = wbuf + coff + a * 5;
                const float o0 = s[0];
                const float o1 = s[1];
                const float o2 = s[2];
                const float o3 = s[3];
                const float obj = s[4];

                const float area_a = (ax2 - ax1) * (ay2 - ay1);
                const float acx = (ax1 + ax2) * 0.5f;
                const float acy = (ay1 + ay2) * 0.5f;

                const float bcx = o0 - 0.5f + zx;
                const float bcy = o1 - 0.5f + zy;
                const float bw  = o2 - 0.5f + (1.0f / GXN);
                const float bh  = o3 - 0.5f + (1.0f / GYN);
                const float bx1 = bcx - bw * 0.5f;
                const float bx2 = bcx + bw * 0.5f;
                const float by1 = bcy - bh * 0.5f;
                const float by2 = bcy + bh * 0.5f;

                const float iw = fminf(ax2, bx2) - fmaxf(ax1, bx1);
                const float ih = fminf(ay2, by2) - fmaxf(ay1, by1);
                const float cross = (iw > 0.0f && ih > 0.0f) ? iw * ih : 0.0f;
                const float area_b = (bx2 - bx1) * (by2 - by1);
                const float uni = area_a + area_b - cross;
                const float iou = __fdividef(cross, uni + 1e-6f);

                const float dx = bcx - acx;
                const float dy = bcy - acy;
                const float d2 = dx * dx + dy * dy;

                const float cw = fmaxf(ax2, bx2) - fminf(ax1, bx1);
                const float ch = fmaxf(ay2, by2) - fminf(ay1, by1);
                const float c2 = cw * cw + ch * ch;

                const float diou = iou - __fdividef(d2, c2);

                const float da = atana - atanf(__fdividef(bx2 - bx1, by2 - by1));
                const float v = FOUR_OVER_PI2 * da * da;
                const float alpha = __fdividef(v, 1.0f - iou + v);
                const float los = 1.0f - (diou - alpha * v);

                const float om = 1.0f - obj;
                acc_allloss += los + om;
                acc_jbb += iou;
                acc_huhuh += om;
                acc_zsd += om * om;
            }
        }

        // ---- Buffer free; refill with tile i+NBUF (queue stays >=2 deep) ----
        __syncthreads();
        if (tid == 0 && i + NBUF < nt) {
            issue_tile(out, target, bid + (i + NBUF) * GRID,
                       buf_base + b * BUF_BYTES, mbar_base + b * 8);
        }

        if (++b == NBUF) { b = 0; phase ^= 1u; }
    }

    // ---- Block reduction (once per block) ----
    float vals[5];
    vals[0] = acc_allloss;
    vals[1] = acc_jbb;
    vals[2] = acc_huhuh;
    vals[3] = acc_zsd;
    vals[4] = acc_npos;

    #pragma unroll
    for (int kk = 0; kk < 5; kk++) {
        float v = vals[kk];
        v += __shfl_xor_sync(FULL, v, 16);
        v += __shfl_xor_sync(FULL, v, 8);
        v += __shfl_xor_sync(FULL, v, 4);
        v += __shfl_xor_sync(FULL, v, 2);
        v += __shfl_xor_sync(FULL, v, 1);
        vals[kk] = v;
    }
    if (lane == 0) {
        #pragma unroll
        for (int kk = 0; kk < 5; kk++) s_red[warp][kk] = vals[kk];
    }
    __syncthreads();

    if (warp == 0 && lane < 5) {
        float v = 0.0f;
        #pragma unroll
        for (int w = 0; w < NWARPS; w++) v += s_red[w][lane];
        atomicAdd(&g_acc[lane], (double)v);
    }
    __syncthreads();

    // ---- Last block finalizes and resets for next graph replay ----
    if (tid == 0) {
        __threadfence();
        const unsigned done = atomicAdd(&g_count, 1u);
        s_islast = (done == (unsigned)(gridDim.x - 1)) ? 1 : 0;
    }
    __syncthreads();

    if (s_islast && tid == 0) {
        const double a0 = atomicAdd(&g_acc[0], 0.0);
        const double a1 = atomicAdd(&g_acc[1], 0.0);
        const double a2 = atomicAdd(&g_acc[2], 0.0);
        const double a3 = atomicAdd(&g_acc[3], 0.0);
        const double npos = atomicAdd(&g_acc[4], 0.0);

        const double jsq = npos * (double)NA;
        const double qit = ((double)NCELLS - npos) * (double)NA;
        o[0] = (float)(a0 / jsq + a3 / (jsq + qit));
        o[1] = (float)(a1 / jsq);
        o[2] = (float)(a2 / jsq);

        g_acc[0] = 0.0; g_acc[1] = 0.0; g_acc[2] = 0.0;
        g_acc[3] = 0.0; g_acc[4] = 0.0;
        __threadfence();
        g_count = 0u;
    }
}

extern "C" void kernel_launch(void* const* d_in, const int* in_sizes, int n_in,
                              void* d_out, int out_size) {
    const float* out_t = (const float*)d_in[0];
    const float* target = (const float*)d_in[1];
    float* o = (float*)d_out;

    const int smem_bytes = NBUF * BUF_FLOATS * (int)sizeof(float); // 96768
    static int configured = 0;
    if (!configured) {
        cudaFuncSetAttribute(loss_kernel,
                             cudaFuncAttributeMaxDynamicSharedMemorySize,
                             smem_bytes);
        configured = 1;
    }
    loss_kernel<<<GRID, TPB, smem_bytes>>>(out_t, target, o);
}

// round 15
// speedup vs baseline: 1.2832x; 1.0450x over previous
#include <cuda_runtime.h>
#include <cuda.h>
#include <math.h>

#define GXN 128
#define GYN 128
#define NA 9
#define NCELLS (32 * 128 * 128)            // 524288
#define TPB 128
#define NWARPS (TPB / 32)                  // 4
#define TILE_CELLS 128
#define NTILES (NCELLS / TILE_CELLS)       // 4096
#define OUT_FLOATS (TILE_CELLS * 45)       // 5760
#define OUT_BYTES (OUT_FLOATS * 4)         // 23040 (multiple of 128)
#define TGT_ROWF 28                        // floats per TMA row (2 cells)
#define TGT_ROWS (TILE_CELLS / 2)          // 64
#define TGT_FLOATS (TGT_ROWS * TGT_ROWF)   // 1792
#define TGT_BYTES (TGT_FLOATS * 4)         // 7168
#define BUF_FLOATS (OUT_FLOATS + TGT_FLOATS) // 7552
#define BUF_BYTES (BUF_FLOATS * 4)         // 30208 (multiple of 128)
#define NBUF 2
#define GRID 444                           // 3 CTAs/SM * 148 SMs

__device__ double g_acc[5];
__device__ unsigned int g_count = 0;

__device__ __forceinline__ unsigned smem_u32(const void* p) {
    return (unsigned)__cvta_generic_to_shared(p);
}
__device__ __forceinline__ void mbar_init(unsigned mbar, unsigned count) {
    asm volatile("mbarrier.init.shared.b64 [%0], %1;" :: "r"(mbar), "r"(count) : "memory");
}
__device__ __forceinline__ void mbar_expect_tx(unsigned mbar, unsigned bytes) {
    asm volatile("mbarrier.arrive.expect_tx.shared.b64 _, [%0], %1;"
                 :: "r"(mbar), "r"(bytes) : "memory");
}
__device__ __forceinline__ void bulk_copy(unsigned dst_smem, const void* gsrc,
                                          unsigned bytes, unsigned mbar) {
    asm volatile(
        "cp.async.bulk.shared::cta.global.mbarrier::complete_tx::bytes [%0], [%1], %2, [%3];"
        :: "r"(dst_smem), "l"(gsrc), "r"(bytes), "r"(mbar) : "memory");
}
__device__ __forceinline__ void tma_load_2d(unsigned dst_smem, const CUtensorMap* tmap,
                                            int cx, int cy, unsigned mbar) {
    asm volatile(
        "cp.async.bulk.tensor.2d.shared::cta.global.tile.mbarrier::complete_tx::bytes "
        "[%0], [%1, {%2, %3}], [%4];"
        :: "r"(dst_smem), "l"(tmap), "r"(cx), "r"(cy), "r"(mbar) : "memory");
}
__device__ __forceinline__ void mbar_wait(unsigned mbar, unsigned phase) {
    unsigned done;
    asm volatile(
        "{\n\t.reg .pred p;\n\t"
        "mbarrier.try_wait.parity.acquire.cta.shared::cta.b64 p, [%1], %2;\n\t"
        "selp.b32 %0, 1, 0, p;\n\t}"
        : "=r"(done) : "r"(mbar), "r"(phase) : "memory");
    if (!done) {
        asm volatile(
            "{\n\t.reg .pred P1;\n\t"
            "WAIT_LOOP_%=:\n\t"
            "mbarrier.try_wait.parity.acquire.cta.shared::cta.b64 P1, [%0], %1, 0x989680;\n\t"
            "@P1 bra.uni WAIT_DONE_%=;\n\t"
            "bra.uni WAIT_LOOP_%=;\n\t"
            "WAIT_DONE_%=:\n\t}"
            :: "r"(mbar), "r"(phase) : "memory");
    }
}

__global__ __launch_bounds__(TPB) void loss_kernel(
    const float* __restrict__ out,
    const float* __restrict__ target,
    const __grid_constant__ CUtensorMap tmap,
    const int use_tma,
    float* __restrict__ o)
{
    extern __shared__ __align__(128) float s_buf[];  // NBUF*7552 floats = 60416 B
    // per slot: [0:5760) out tile, [5760:7552) target rows (28 floats / 2 cells)

    __shared__ float s_cellp[NWARPS][32][8];
    __shared__ float s_red[NWARPS][5];
    __shared__ int s_islast;
    __shared__ __align__(8) unsigned long long s_mbar[NBUF];

    const int tid = threadIdx.x;
    const int warp = tid >> 5;
    const int lane = tid & 31;
    const unsigned FULL = 0xFFFFFFFFu;

    const unsigned mbar_base = smem_u32(&s_mbar[0]);
    const unsigned buf_base = smem_u32(s_buf);
    const unsigned txbytes = OUT_BYTES + (use_tma ? TGT_BYTES : 0);

    const int bid = blockIdx.x;
    const int nt = (bid < NTILES % GRID) ? (NTILES / GRID + 1) : (NTILES / GRID);

    if (tid < NBUF) mbar_init(mbar_base + tid * 8, 1);
    __syncthreads();

    if (tid == 0) {
        #pragma unroll
        for (int b = 0; b < NBUF; b++) {
            if (b < nt) {
                const int tile = bid + b * GRID;
                const unsigned d = buf_base + b * BUF_BYTES;
                const unsigned mb = mbar_base + b * 8;
                mbar_expect_tx(mb, txbytes);
                bulk_copy(d, out + (size_t)tile * OUT_FLOATS, OUT_BYTES, mb);
                if (use_tma)
                    tma_load_2d(d + OUT_BYTES, &tmap, 0, tile * TGT_ROWS, mb);
            }
        }
    }

    float acc_allloss = 0.0f;
    float acc_jbb = 0.0f;
    float acc_huhuh = 0.0f;
    float acc_zsd = 0.0f;
    float acc_npos = 0.0f;

    const float FOUR_OVER_PI2 = 4.0f / (3.14159265358979323846f * 3.14159265358979323846f);

    for (int i = 0; i < nt; i++) {
        const int tile = bid + i * GRID;
        const int b = i & 1;
        const unsigned phase = (i >> 1) & 1u;
        float* bb = s_buf + b * BUF_FLOATS;
        float* wbuf = bb + warp * (32 * 45);

        const int ct = warp * 32 + lane;            // cell index within tile
        const int cellc = tile * TILE_CELLS + ct;

        // Fallback path: per-lane scattered target loads, issued before the wait
        float f_st0 = 0.f, f_st1 = 0.f, f_st2 = 0.f, f_st3 = 0.f, f_st5 = 0.f;
        if (!use_tma) {
            const float* st = target + (size_t)cellc * 18;
            const float2 a = __ldg(reinterpret_cast<const float2*>(st));
            const float2 c = __ldg(reinterpret_cast<const float2*>(st + 2));
            f_st0 = a.x; f_st1 = a.y; f_st2 = c.x; f_st3 = c.y;
            f_st5 = __ldg(st + 5);
        }

        mbar_wait(mbar_base + b * 8, phase);

        float st0, st1, st2, st3, st5;
        if (use_tma) {
            const float* stg = bb + OUT_FLOATS + (ct >> 1) * TGT_ROWF + (ct & 1) * 18;
            st0 = stg[0]; st1 = stg[1]; st2 = stg[2]; st3 = stg[3]; st5 = stg[5];
        } else {
            st0 = f_st0; st1 = f_st1; st2 = f_st2; st3 = f_st3; st5 = f_st5;
        }

        const bool pos = st5 > 0.8f;
        const unsigned m = __ballot_sync(FULL, pos);
        const int nP = __popc(m);

        if (pos) {
            const int off = __popc(m & ((1u << lane) - 1u));
            const int gy = cellc & 127;
            const int gx = (cellc >> 7) & 127;

            const float ax1 = st0 - st2 * 0.5f;
            const float ax2 = st0 + st2 * 0.5f;
            const float ay1 = st1 - st3 * 0.5f;
            const float ay2 = st1 + st3 * 0.5f;
            const float atana = atanf(__fdividef(ax2 - ax1, ay2 - ay1));
            const float zx = (float)gx * (1.0f / GXN) + 1.0f / (2.0f * GXN);
            const float zy = (float)gy * (1.0f / GYN) + 1.0f / (2.0f * GYN);

            float* p = s_cellp[warp][off];
            p[0] = ax1; p[1] = ax2; p[2] = ay1; p[3] = ay2;
            p[4] = atana; p[5] = zx; p[6] = zy;
            p[7] = __int_as_float(lane * 45);
            acc_npos += 1.0f;
        } else {
            const float* s = wbuf + lane * 45;
            #pragma unroll
            for (int a = 0; a < NA; a++) {
                const float obj = s[a * 5 + 4];
                acc_zsd += obj * obj;
            }
        }
        __syncwarp();

        // ---- Heavy sweep: nP*9 work items across this warp's 32 cells ----
        const int items = nP * NA;
        for (int bo = 0; bo < items; bo += 32) {
            const int ii = bo + lane;
            if (ii < items) {
                const int r = ii / 9;
                const int a = ii - r * 9;
                const float* p = s_cellp[warp][r];
                const float ax1 = p[0], ax2 = p[1], ay1 = p[2], ay2 = p[3];
                const float atana = p[4], zx = p[5], zy = p[6];
                const int coff = __float_as_int(p[7]);

                const float* s = wbuf + coff + a * 5;
                const float o0 = s[0];
                const float o1 = s[1];
                const float o2 = s[2];
                const float o3 = s[3];
                const float obj = s[4];

                const float area_a = (ax2 - ax1) * (ay2 - ay1);
                const float acx = (ax1 + ax2) * 0.5f;
                const float acy = (ay1 + ay2) * 0.5f;

                const float bcx = o0 - 0.5f + zx;
                const float bcy = o1 - 0.5f + zy;
                const float bw  = o2 - 0.5f + (1.0f / GXN);
                const float bh  = o3 - 0.5f + (1.0f / GYN);
                const float bx1 = bcx - bw * 0.5f;
                const float bx2 = bcx + bw * 0.5f;
                const float by1 = bcy - bh * 0.5f;
                const float by2 = bcy + bh * 0.5f;

                const float iw = fminf(ax2, bx2) - fmaxf(ax1, bx1);
                const float ih = fminf(ay2, by2) - fmaxf(ay1, by1);
                const float cross = (iw > 0.0f && ih > 0.0f) ? iw * ih : 0.0f;
                const float area_b = (bx2 - bx1) * (by2 - by1);
                const float uni = area_a + area_b - cross;
                const float iou = __fdividef(cross, uni + 1e-6f);

                const float dx = bcx - acx;
                const float dy = bcy - acy;
                const float d2 = dx * dx + dy * dy;

                const float cw = fmaxf(ax2, bx2) - fminf(ax1, bx1);
                const float ch = fmaxf(ay2, by2) - fminf(ay1, by1);
                const float c2 = cw * cw + ch * ch;

                const float diou = iou - __fdividef(d2, c2);

                const float da = atana - atanf(__fdividef(bx2 - bx1, by2 - by1));
                const float v = FOUR_OVER_PI2 * da * da;
                const float alpha = __fdividef(v, 1.0f - iou + v);
                const float los = 1.0f - (diou - alpha * v);

                const float om = 1.0f - obj;
                acc_allloss += los + om;
                acc_jbb += iou;
                acc_huhuh += om;
                acc_zsd += om * om;
            }
        }

        // ---- Buffer free; refill with tile i+2 ----
        __syncthreads();
        if (tid == 0 && i + NBUF < nt) {
            const int tn = bid + (i + NBUF) * GRID;
            const unsigned d = buf_base + b * BUF_BYTES;
            const unsigned mb = mbar_base + b * 8;
            mbar_expect_tx(mb, txbytes);
            bulk_copy(d, out + (size_t)tn * OUT_FLOATS, OUT_BYTES, mb);
            if (use_tma)
                tma_load_2d(d + OUT_BYTES, &tmap, 0, tn * TGT_ROWS, mb);
        }
    }

    // ---- Block reduction (once per block) ----
    float vals[5];
    vals[0] = acc_allloss;
    vals[1] = acc_jbb;
    vals[2] = acc_huhuh;
    vals[3] = acc_zsd;
    vals[4] = acc_npos;

    #pragma unroll
    for (int kk = 0; kk < 5; kk++) {
        float v = vals[kk];
        v += __shfl_xor_sync(FULL, v, 16);
        v += __shfl_xor_sync(FULL, v, 8);
        v += __shfl_xor_sync(FULL, v, 4);
        v += __shfl_xor_sync(FULL, v, 2);
        v += __shfl_xor_sync(FULL, v, 1);
        vals[kk] = v;
    }
    if (lane == 0) {
        #pragma unroll
        for (int kk = 0; kk < 5; kk++) s_red[warp][kk] = vals[kk];
    }
    __syncthreads();

    if (warp == 0 && lane < 5) {
        float v = 0.0f;
        #pragma unroll
        for (int w = 0; w < NWARPS; w++) v += s_red[w][lane];
        atomicAdd(&g_acc[lane], (double)v);
    }
    __syncthreads();

    if (tid == 0) {
        __threadfence();
        const unsigned done = atomicAdd(&g_count, 1u);
        s_islast = (done == (unsigned)(gridDim.x - 1)) ? 1 : 0;
    }
    __syncthreads();

    if (s_islast && tid == 0) {
        const double a0 = atomicAdd(&g_acc[0], 0.0);
        const double a1 = atomicAdd(&g_acc[1], 0.0);
        const double a2 = atomicAdd(&g_acc[2], 0.0);
        const double a3 = atomicAdd(&g_acc[3], 0.0);
        const double npos = atomicAdd(&g_acc[4], 0.0);

        const double jsq = npos * (double)NA;
        const double qit = ((double)NCELLS - npos) * (double)NA;
        o[0] = (float)(a0 / jsq + a3 / (jsq + qit));
        o[1] = (float)(a1 / jsq);
        o[2] = (float)(a2 / jsq);

        g_acc[0] = 0.0; g_acc[1] = 0.0; g_acc[2] = 0.0;
        g_acc[3] = 0.0; g_acc[4] = 0.0;
        __threadfence();
        g_count = 0u;
    }
}

extern "C" void kernel_launch(void* const* d_in, const int* in_sizes, int n_in,
                              void* d_out, int out_size) {
    const float* out_t = (const float*)d_in[0];
    const float* target = (const float*)d_in[1];
    float* o = (float*)d_out;

    typedef CUresult (*EncodeFn)(
        CUtensorMap*, CUtensorMapDataType, cuuint32_t, void*,
        const cuuint64_t*, const cuuint64_t*, const cuuint32_t*, const cuuint32_t*,
        CUtensorMapInterleave, CUtensorMapSwizzle, CUtensorMapL2promotion,
        CUtensorMapFloatOOBfill);

    static int configured = 0;
    static int use_tma = 0;
    alignas(64) static CUtensorMap g_tmap;

    const int smem_bytes = NBUF * BUF_FLOATS * (int)sizeof(float); // 60416
    if (!configured) {
        cudaFuncSetAttribute(loss_kernel,
                             cudaFuncAttributeMaxDynamicSharedMemorySize,
                             smem_bytes);
        void* fn = 0;
        cudaDriverEntryPointQueryResult qr;
#if CUDART_VERSION >= 12050
        cudaGetDriverEntryPointByVersion("cuTensorMapEncodeTiled", &fn, 12000,
                                         cudaEnableDefault, &qr);
#else
        cudaGetDriverEntryPoint("cuTensorMapEncodeTiled", &fn,
                                cudaEnableDefault, &qr);
#endif
        if (fn) {
            // target viewed as [NCELLS/2 rows] x [36 floats], stride 144 B (mult of 16)
            cuuint64_t dims[2] = {36, (cuuint64_t)(NCELLS / 2)};
            cuuint64_t strides[1] = {36 * sizeof(float)};   // 144 B
            cuuint32_t box[2] = {TGT_ROWF, TGT_ROWS};       // 28 floats (112 B) x 64 rows
            cuuint32_t es[2] = {1, 1};
            CUresult rc = ((EncodeFn)fn)(&g_tmap, CU_TENSOR_MAP_DATA_TYPE_FLOAT32, 2,
                                         (void*)target, dims, strides, box, es,
                                         CU_TENSOR_MAP_INTERLEAVE_NONE,
                                         CU_TENSOR_MAP_SWIZZLE_NONE,
                                         CU_TENSOR_MAP_L2_PROMOTION_L2_128B,
                                         CU_TENSOR_MAP_FLOAT_OOB_FILL_NONE);
            use_tma = (rc == CUDA_SUCCESS) ? 1 : 0;
        }
        configured = 1;
    }
    loss_kernel<<<GRID, TPB, smem_bytes>>>(out_t, target, g_tmap, use_tma, o);
}